// round 2
// baseline (speedup 1.0000x reference)
#include <cuda_runtime.h>

// Problem constants
#define TT   1200      // time length
#define NF   10        // conv filters
#define KK   17        // conv kernel width (pad 8 both sides)
#define NCH  80        // 15-wide chunks per row (1200/15)
#define NTP  76        // pooled length: (1200-75)/15+1
#define FEAT (NF*NTP)  // 760
#define ROWS 2         // (b,m) rows per block
#define THREADS 256

__global__ __launch_bounds__(THREADS) void scorer_kernel(
    const float* __restrict__ x,       // (B,1,M,T) -> row-major rows of 1200
    const float* __restrict__ conv_w,  // (NF,1,KK)
    const float* __restrict__ conv_b,  // (NF)
    const float* __restrict__ lin_w,   // (M, FEAT)
    const float* __restrict__ lin_b,   // (M)
    float* __restrict__ out)           // (B,M,1) -> 16384 floats
{
    __shared__ float s_x[ROWS][TT + 16];   // 8-zero halo each side
    __shared__ float s_w[NF * KK];
    __shared__ float s_cb[NF];
    __shared__ float s_S[ROWS][NF * NCH];  // 15-chunk sums of conv^2
    __shared__ float s_out[ROWS];

    const int tid  = threadIdx.x;
    const int row0 = blockIdx.x * ROWS;    // row = b*64 + m
    const int m0   = row0 & 63;

    // ---- Phase 0: stage weights, halo zeros, x rows ----
    for (int i = tid; i < NF * KK; i += THREADS) s_w[i] = conv_w[i];
    if (tid < NF)   s_cb[tid]  = conv_b[tid];
    if (tid < ROWS) s_out[tid] = 0.f;
    if (tid < ROWS * 16) {
        int r = tid >> 4, j = tid & 15;
        if (j < 8) s_x[r][j] = 0.f;        // left halo [0..7]
        else       s_x[r][TT + j] = 0.f;   // right halo [1208..1215]
    }
    for (int i = tid; i < ROWS * TT; i += THREADS) {
        int r = i / TT, t = i - r * TT;    // consecutive t -> coalesced
        s_x[r][8 + t] = x[(size_t)(row0 + r) * TT + t];
    }
    __syncthreads();

    // ---- Phase 1: conv -> +bias -> square -> 15-chunk partial sums ----
    // task = (row r, filter f, chunk i); each task: 15 conv outputs, all in regs.
    for (int task = tid; task < ROWS * NF * NCH; task += THREADS) {
        int r   = task / (NF * NCH);
        int rem = task - r * (NF * NCH);
        int f   = rem / NCH;
        int i   = rem - f * NCH;

        const float* xp = &s_x[r][i * 15]; // xs[0] corresponds to t = -8
        float w[KK];
        #pragma unroll
        for (int k = 0; k < KK; ++k) w[k] = s_w[f * KK + k];
        const float bias = s_cb[f];

        float S = 0.f;
        #pragma unroll
        for (int s = 0; s < 3; ++s) {      // 3 strips of 5 outputs
            float xv[21];
            #pragma unroll
            for (int j = 0; j < 21; ++j) xv[j] = xp[s * 5 + j];
            #pragma unroll
            for (int j = 0; j < 5; ++j) {
                float c = bias;
                #pragma unroll
                for (int k = 0; k < KK; ++k) c = fmaf(xv[j + k], w[k], c);
                S = fmaf(c, c, S);
            }
        }
        s_S[r][f * NCH + i] = S;
    }
    __syncthreads();

    // ---- Phase 2: pool(= 5 chunk sums)/75 -> log -> dot with lin_w ----
    float part0 = 0.f, part1 = 0.f;
    for (int task = tid; task < ROWS * NF * NTP; task += THREADS) {
        int r   = task / (NF * NTP);
        int rem = task - r * (NF * NTP);   // rem = f*NTP + tp = feature index
        int f   = rem / NTP;
        int tp  = rem - f * NTP;

        const float* Sp = &s_S[r][f * NCH + tp];
        float p = (((Sp[0] + Sp[1]) + (Sp[2] + Sp[3])) + Sp[4]) * (1.0f / 75.0f);
        p = fmaxf(p, 1e-10f);
        float v  = __logf(p);
        float lw = lin_w[(m0 + r) * FEAT + rem];
        if (r == 0) part0 = fmaf(v, lw, part0);
        else        part1 = fmaf(v, lw, part1);
    }
    #pragma unroll
    for (int off = 16; off > 0; off >>= 1) {
        part0 += __shfl_down_sync(0xffffffffu, part0, off);
        part1 += __shfl_down_sync(0xffffffffu, part1, off);
    }
    if ((tid & 31) == 0) {
        atomicAdd(&s_out[0], part0);
        atomicAdd(&s_out[1], part1);
    }
    __syncthreads();

    if (tid < ROWS) out[row0 + tid] = s_out[tid] + lin_b[m0 + tid];
}

extern "C" void kernel_launch(void* const* d_in, const int* in_sizes, int n_in,
                              void* d_out, int out_size) {
    const float* x      = (const float*)d_in[0];
    const float* conv_w = (const float*)d_in[1];
    const float* conv_b = (const float*)d_in[2];
    const float* lin_w  = (const float*)d_in[3];
    const float* lin_b  = (const float*)d_in[4];
    float* out = (float*)d_out;

    const int n_rows = 256 * 64;                 // B*M
    scorer_kernel<<<n_rows / ROWS, THREADS>>>(x, conv_w, conv_b, lin_w, lin_b, out);
}

// round 3
// speedup vs baseline: 1.2057x; 1.2057x over previous
#include <cuda_runtime.h>

// Problem constants
#define TT    1200              // time length
#define NF    10                // conv filters
#define KK    17                // conv kernel width (pad 8 both sides)
#define NSTR  240               // 5-wide output strips per row (1200/5)
#define NTP   76                // pooled length
#define NTPG  19                // groups of 4 pooled outputs (76/4)
#define FEAT  (NF*NTP)          // 760
#define ROWS  2                 // (b,m) rows per block (the f32x2 SIMD pair)
#define THREADS 256

typedef unsigned long long u64;

__device__ __forceinline__ u64 pack2(float lo, float hi) {
    u64 r;
    asm("mov.b64 %0, {%1, %2};" : "=l"(r) : "f"(lo), "f"(hi));
    return r;
}
__device__ __forceinline__ void unpack2(u64 v, float& lo, float& hi) {
    asm("mov.b64 {%0, %1}, %2;" : "=f"(lo), "=f"(hi) : "l"(v));
}
__device__ __forceinline__ u64 ffma2(u64 a, u64 b, u64 c) {
    u64 d;
    asm("fma.rn.f32x2 %0, %1, %2, %3;" : "=l"(d) : "l"(a), "l"(b), "l"(c));
    return d;
}

__global__ __launch_bounds__(THREADS, 2) void scorer_kernel(
    const float* __restrict__ x,       // (B,1,M,T) rows of 1200
    const float* __restrict__ conv_w,  // (NF,1,KK)
    const float* __restrict__ conv_b,  // (NF)
    const float* __restrict__ lin_w,   // (M, FEAT)
    const float* __restrict__ lin_b,   // (M)
    float* __restrict__ out)           // (B,M,1)
{
    __shared__ u64   s_x2[TT + 16];        // {row0,row1} pairs, 8-zero halo each side
    __shared__ u64   s_w2[NF * KK];        // {w,w}
    __shared__ u64   s_b2[NF];             // {b,b}
    __shared__ float s_S[ROWS][NF * NSTR]; // 5-strip sums of conv^2
    __shared__ float s_out[ROWS];

    const int tid  = threadIdx.x;
    const int row0 = blockIdx.x * ROWS;    // row = b*64 + m
    const int m0   = row0 & 63;

    // ---- Phase 0: stage packed weights, halos, interleaved x rows ----
    for (int i = tid; i < NF * KK; i += THREADS) { float w = conv_w[i]; s_w2[i] = pack2(w, w); }
    if (tid < NF)   { float b = conv_b[tid]; s_b2[tid] = pack2(b, b); }
    if (tid < ROWS) s_out[tid] = 0.f;
    if (tid >= THREADS - 16) {
        int j = tid - (THREADS - 16);
        if (j < 8) s_x2[j] = 0ull;             // left halo
        else       s_x2[TT + j] = 0ull;        // right halo
    }
    {
        const float* xr0 = x + (size_t)row0 * TT;
        const float* xr1 = xr0 + TT;
        for (int t = tid; t < TT; t += THREADS)
            s_x2[8 + t] = pack2(xr0[t], xr1[t]);   // coalesced within each row
    }
    __syncthreads();

    // ---- Phase 1: per 5-output strip, ALL filters: conv -> +b -> square -> strip sum ----
    if (tid < NSTR) {
        const int s = tid;
        const u64* xp = &s_x2[5 * s];          // window x[5s-8 .. 5s+12]
        u64 xv[21];
        #pragma unroll
        for (int j = 0; j < 21; ++j) xv[j] = xp[j];

        for (int f = 0; f < NF; ++f) {
            const u64* wp = &s_w2[f * KK];
            const u64 b2 = s_b2[f];
            u64 c0 = b2, c1 = b2, c2 = b2, c3 = b2, c4 = b2;
            #pragma unroll
            for (int k = 0; k < KK; ++k) {
                const u64 wk = wp[k];          // broadcast LDS.64
                c0 = ffma2(xv[k    ], wk, c0);
                c1 = ffma2(xv[k + 1], wk, c1);
                c2 = ffma2(xv[k + 2], wk, c2);
                c3 = ffma2(xv[k + 3], wk, c3);
                c4 = ffma2(xv[k + 4], wk, c4);
            }
            u64 S = ffma2(c0, c0, 0ull);       // {0,0} bit pattern == {0.f,0.f}
            S = ffma2(c1, c1, S);
            S = ffma2(c2, c2, S);
            S = ffma2(c3, c3, S);
            S = ffma2(c4, c4, S);
            float S0, S1; unpack2(S, S0, S1);
            s_S[0][f * NSTR + s] = S0;
            s_S[1][f * NSTR + s] = S1;
        }
    }
    __syncthreads();

    // ---- Phase 2: sliding pool (15 strips per window, hop 3) -> log -> dot ----
    float part0 = 0.f, part1 = 0.f;
    for (int task = tid; task < ROWS * NF * NTPG; task += THREADS) {   // 380 tasks
        int r   = task / (NF * NTPG);
        int rem = task - r * (NF * NTPG);
        int f   = rem / NTPG;
        int g   = rem - f * NTPG;              // covers tp = 4g .. 4g+3

        const float* Sp = &s_S[r][f * NSTR + 12 * g];
        float sv[24];
        #pragma unroll
        for (int j = 0; j < 24; ++j) sv[j] = Sp[j];

        float run = 0.f;
        #pragma unroll
        for (int j = 0; j < 15; ++j) run += sv[j];

        const float4 lw = *(const float4*)&lin_w[(size_t)(m0 + r) * FEAT + f * NTP + 4 * g];
        float acc = 0.f;
        #pragma unroll
        for (int q = 0; q < 4; ++q) {
            float p = fmaxf(run * (1.0f / 75.0f), 1e-10f);
            float v = __logf(p);
            float w = (q == 0) ? lw.x : (q == 1) ? lw.y : (q == 2) ? lw.z : lw.w;
            acc = fmaf(v, w, acc);
            if (q < 3) {
                run += (sv[15 + 3*q] + sv[16 + 3*q] + sv[17 + 3*q])
                     - (sv[3*q] + sv[1 + 3*q] + sv[2 + 3*q]);
            }
        }
        if (r == 0) part0 += acc; else part1 += acc;
    }
    #pragma unroll
    for (int off = 16; off > 0; off >>= 1) {
        part0 += __shfl_down_sync(0xffffffffu, part0, off);
        part1 += __shfl_down_sync(0xffffffffu, part1, off);
    }
    if ((tid & 31) == 0) {
        atomicAdd(&s_out[0], part0);
        atomicAdd(&s_out[1], part1);
    }
    __syncthreads();

    if (tid < ROWS) out[row0 + tid] = s_out[tid] + lin_b[m0 + tid];
}

extern "C" void kernel_launch(void* const* d_in, const int* in_sizes, int n_in,
                              void* d_out, int out_size) {
    const float* x      = (const float*)d_in[0];
    const float* conv_w = (const float*)d_in[1];
    const float* conv_b = (const float*)d_in[2];
    const float* lin_w  = (const float*)d_in[3];
    const float* lin_b  = (const float*)d_in[4];
    float* out = (float*)d_out;

    const int n_rows = 256 * 64;               // B*M
    scorer_kernel<<<n_rows / ROWS, THREADS>>>(x, conv_w, conv_b, lin_w, lin_b, out);
}